// round 15
// baseline (speedup 1.0000x reference)
#include <cuda_runtime.h>

// param_distance: K=8, B=32, N=4096, D=64 ; BN = 131072
// out[row] = agg[argmin_k sum_d |t[row,d]-agg[k,row,d]|, row, 0]
//
// FINAL (converged, 8 confirming samples): warp-per-row, float2 per lane,
// 9 batched streaming loads (MLP=9, fully-coalesced 256B transactions),
// split-butterfly reduction (9 SHFLs for all 8 candidate sums) + argmin
// butterfly with first-index tie-break (6 SHFLs). 128-thread blocks
// (block-size bracket: 128 ~= 256 > 512).
// Distribution over identical/equivalent source: harness 45.5-47.1 us
// (median 45.6), ncu kernel 44.96-46.6 us, DRAM 82.9-85.9% (6.6-6.8 TB/s)
// — the sustained HBM-efficiency ceiling for this 9-stream once-touched
// read pattern on GB300. All structural alternatives measured at or below
// this baseline over 14 rounds.

__global__ __launch_bounds__(128, 16)
void param_distance_kernel(const float* __restrict__ tensor,
                           const float* __restrict__ agg,
                           float* __restrict__ out,
                           int BN)
{
    const int row  = blockIdx.x * (blockDim.x >> 5) + (threadIdx.x >> 5);
    const int lane = threadIdx.x & 31;
    if (row >= BN) return;

    const size_t rbase   = (size_t)row * 64;
    const size_t kstride = (size_t)BN * 64;

    const float2 tv = __ldcs(reinterpret_cast<const float2*>(tensor + rbase + lane * 2));

    float2 av[8];
#pragma unroll
    for (int k = 0; k < 8; ++k)
        av[k] = __ldcs(reinterpret_cast<const float2*>(agg + (size_t)k * kstride + rbase + lane * 2));

    float p[8];
#pragma unroll
    for (int k = 0; k < 8; ++k)
        p[k] = fabsf(tv.x - av[k].x) + fabsf(tv.y - av[k].y);

    // ---- split butterfly: distribute the 8 sums across lane groups ----
    // stage 1 (xor 16): low half keeps k0..3, high half keeps k4..7
    const bool hi16 = (lane & 16) != 0;
    float q[4];
#pragma unroll
    for (int j = 0; j < 4; ++j) {
        float send = hi16 ? p[j] : p[j + 4];
        float recv = __shfl_xor_sync(0xFFFFFFFFu, send, 16);
        q[j] = (hi16 ? p[j + 4] : p[j]) + recv;
    }
    const bool hi8 = (lane & 8) != 0;
    float r[2];
#pragma unroll
    for (int j = 0; j < 2; ++j) {
        float send = hi8 ? q[j] : q[j + 2];
        float recv = __shfl_xor_sync(0xFFFFFFFFu, send, 8);
        r[j] = (hi8 ? q[j + 2] : q[j]) + recv;
    }
    const bool hi4 = (lane & 4) != 0;
    float s;
    {
        float send = hi4 ? r[0] : r[1];
        float recv = __shfl_xor_sync(0xFFFFFFFFu, send, 4);
        s = (hi4 ? r[1] : r[0]) + recv;
    }
    // finish the sum within each 4-lane replica group
    s += __shfl_xor_sync(0xFFFFFFFFu, s, 2);
    s += __shfl_xor_sync(0xFFFFFFFFu, s, 1);

    // lane's candidate index: k bit2 = lane bit4, k bit1 = lane bit3, k bit0 = lane bit2
    const int myk = (lane >> 2) & 7;

    // ---- argmin butterfly over offsets 4,8,16 (replicas consistent) ----
    float bv = s;
    int   bk = myk;
#pragma unroll
    for (int off = 4; off <= 16; off <<= 1) {
        float ov = __shfl_xor_sync(0xFFFFFFFFu, bv, off);
        int   ok = __shfl_xor_sync(0xFFFFFFFFu, bk, off);
        if (ov < bv || (ov == bv && ok < bk)) { bv = ov; bk = ok; }
    }
    // all lanes now agree on bk (first-index tie-break preserved)

    if (lane == 0) {
        // feature element 0 of candidate bk lives in lane 0's av[bk].x
        float a0 = av[0].x;
        a0 = (bk == 1) ? av[1].x : a0;
        a0 = (bk == 2) ? av[2].x : a0;
        a0 = (bk == 3) ? av[3].x : a0;
        a0 = (bk == 4) ? av[4].x : a0;
        a0 = (bk == 5) ? av[5].x : a0;
        a0 = (bk == 6) ? av[6].x : a0;
        a0 = (bk == 7) ? av[7].x : a0;
        out[row] = a0;
    }
}

extern "C" void kernel_launch(void* const* d_in, const int* in_sizes, int n_in,
                              void* d_out, int out_size)
{
    const float* tensor = (const float*)d_in[0];   // [B, N, D] fp32
    const float* agg    = (const float*)d_in[1];   // [K, B, N, D] fp32
    float* out          = (float*)d_out;           // [1, B, N, 1] fp32

    const int D  = 64;
    const int BN = in_sizes[0] / D;                // 131072

    const int threads = 128;                       // 4 warps -> 4 rows per block
    const int rows_per_block = threads / 32;
    const int blocks = (BN + rows_per_block - 1) / rows_per_block;

    param_distance_kernel<<<blocks, threads>>>(tensor, agg, out, BN);
}

// round 16
// speedup vs baseline: 1.0007x; 1.0007x over previous
#include <cuda_runtime.h>

// param_distance: K=8, B=32, N=4096, D=64 ; BN = 131072
// out[row] = agg[argmin_k sum_d |t[row,d]-agg[k,row,d]|, row, 0]
//
// FINAL (converged, 10 confirming samples over 15 rounds): warp-per-row,
// float2 per lane, 9 batched streaming loads (MLP=9, fully-coalesced 256B
// transactions), split-butterfly reduction (9 SHFLs for all 8 candidate
// sums) + argmin butterfly with first-index tie-break (6 SHFLs).
// 128-thread blocks (bracket: 128 >= 256 > 512; 128-thr samples posted the
// two best kernel times: 44.90/45.18 us @ DRAM 85.8/85.4%, occ ~90%).
// Distribution: harness 45.5-47.1 us (median 45.6), kernel 44.9-46.6 us,
// DRAM 82.9-85.9% (6.6-6.8 TB/s) — the sustained HBM-efficiency ceiling
// for this 9-stream once-touched read pattern on GB300. All structural
// alternatives (float4/half-warp, persistent, persistent+pipelined,
// 512-thread blocks, cache-policy variants) measured at or below this.

__global__ __launch_bounds__(128, 16)
void param_distance_kernel(const float* __restrict__ tensor,
                           const float* __restrict__ agg,
                           float* __restrict__ out,
                           int BN)
{
    const int row  = blockIdx.x * (blockDim.x >> 5) + (threadIdx.x >> 5);
    const int lane = threadIdx.x & 31;
    if (row >= BN) return;

    const size_t rbase   = (size_t)row * 64;
    const size_t kstride = (size_t)BN * 64;

    const float2 tv = __ldcs(reinterpret_cast<const float2*>(tensor + rbase + lane * 2));

    float2 av[8];
#pragma unroll
    for (int k = 0; k < 8; ++k)
        av[k] = __ldcs(reinterpret_cast<const float2*>(agg + (size_t)k * kstride + rbase + lane * 2));

    float p[8];
#pragma unroll
    for (int k = 0; k < 8; ++k)
        p[k] = fabsf(tv.x - av[k].x) + fabsf(tv.y - av[k].y);

    // ---- split butterfly: distribute the 8 sums across lane groups ----
    // stage 1 (xor 16): low half keeps k0..3, high half keeps k4..7
    const bool hi16 = (lane & 16) != 0;
    float q[4];
#pragma unroll
    for (int j = 0; j < 4; ++j) {
        float send = hi16 ? p[j] : p[j + 4];
        float recv = __shfl_xor_sync(0xFFFFFFFFu, send, 16);
        q[j] = (hi16 ? p[j + 4] : p[j]) + recv;
    }
    const bool hi8 = (lane & 8) != 0;
    float r[2];
#pragma unroll
    for (int j = 0; j < 2; ++j) {
        float send = hi8 ? q[j] : q[j + 2];
        float recv = __shfl_xor_sync(0xFFFFFFFFu, send, 8);
        r[j] = (hi8 ? q[j + 2] : q[j]) + recv;
    }
    const bool hi4 = (lane & 4) != 0;
    float s;
    {
        float send = hi4 ? r[0] : r[1];
        float recv = __shfl_xor_sync(0xFFFFFFFFu, send, 4);
        s = (hi4 ? r[1] : r[0]) + recv;
    }
    // finish the sum within each 4-lane replica group
    s += __shfl_xor_sync(0xFFFFFFFFu, s, 2);
    s += __shfl_xor_sync(0xFFFFFFFFu, s, 1);

    // lane's candidate index: k bit2 = lane bit4, k bit1 = lane bit3, k bit0 = lane bit2
    const int myk = (lane >> 2) & 7;

    // ---- argmin butterfly over offsets 4,8,16 (replicas consistent) ----
    float bv = s;
    int   bk = myk;
#pragma unroll
    for (int off = 4; off <= 16; off <<= 1) {
        float ov = __shfl_xor_sync(0xFFFFFFFFu, bv, off);
        int   ok = __shfl_xor_sync(0xFFFFFFFFu, bk, off);
        if (ov < bv || (ov == bv && ok < bk)) { bv = ov; bk = ok; }
    }
    // all lanes now agree on bk (first-index tie-break preserved)

    if (lane == 0) {
        // feature element 0 of candidate bk lives in lane 0's av[bk].x
        float a0 = av[0].x;
        a0 = (bk == 1) ? av[1].x : a0;
        a0 = (bk == 2) ? av[2].x : a0;
        a0 = (bk == 3) ? av[3].x : a0;
        a0 = (bk == 4) ? av[4].x : a0;
        a0 = (bk == 5) ? av[5].x : a0;
        a0 = (bk == 6) ? av[6].x : a0;
        a0 = (bk == 7) ? av[7].x : a0;
        out[row] = a0;
    }
}

extern "C" void kernel_launch(void* const* d_in, const int* in_sizes, int n_in,
                              void* d_out, int out_size)
{
    const float* tensor = (const float*)d_in[0];   // [B, N, D] fp32
    const float* agg    = (const float*)d_in[1];   // [K, B, N, D] fp32
    float* out          = (float*)d_out;           // [1, B, N, 1] fp32

    const int D  = 64;
    const int BN = in_sizes[0] / D;                // 131072

    const int threads = 128;                       // 4 warps -> 4 rows per block
    const int rows_per_block = threads / 32;
    const int blocks = (BN + rows_per_block - 1) / rows_per_block;

    param_distance_kernel<<<blocks, threads>>>(tensor, agg, out, BN);
}